// round 16
// baseline (speedup 1.0000x reference)
#include <cuda_runtime.h>
#include <cuda_fp16.h>
#include <cstdint>

#define NROWS 16384
#define DIN   512
#define DOUT  256

#define KC2 64
#define KT1 (DIN / KC2)            // 8
#define KT2 (NROWS / KC2)          // 256
#define A2SZ (128 * 128)           // 16 KB  (fp16 SW128)
#define B2SZ (256 * 128)           // 32 KB
#define STG2 (A2SZ + B2SZ)         // 48 KB
#define SMEM2 (1024 + 4 * STG2)

// scratch (packed SW128 tile layout: [kt][256 n-rows x 64 halfs])
__device__ uint4 g_Wp4[DIN * DOUT / 8];    // W packed: 8 tiles
__device__ uint4 g_Hp4[NROWS * DOUT / 8];  // H packed: 256 tiles
__device__ int   g_flags[KT2];             // H tile ready flags

// ---------------- helpers ----------------
__device__ __forceinline__ uint32_t smem_u32(const void* p) {
    uint32_t a;
    asm("{ .reg .u64 t; cvta.to.shared.u64 t, %1; cvt.u32.u64 %0, t; }"
        : "=r"(a) : "l"(p));
    return a;
}
__device__ __forceinline__ void sts64(uint32_t a, uint32_t x, uint32_t y) {
    asm volatile("st.shared.v2.b32 [%0], {%1, %2};" :: "r"(a), "r"(x), "r"(y) : "memory");
}
__device__ __forceinline__ uint32_t pack2(float x, float y) {
    __half2 h = __floats2half2_rn(x, y);
    return *reinterpret_cast<uint32_t*>(&h);
}
__device__ __forceinline__ void ldsm4(uint32_t* r, uint32_t addr) {
    asm volatile("ldmatrix.sync.aligned.m8n8.x4.shared.b16 {%0,%1,%2,%3}, [%4];"
                 : "=r"(r[0]), "=r"(r[1]), "=r"(r[2]), "=r"(r[3]) : "r"(addr));
}
__device__ __forceinline__ void mma16816(float* d, const uint32_t* a,
                                         uint32_t b0, uint32_t b1) {
    asm volatile(
        "mma.sync.aligned.m16n8k16.row.col.f32.f16.f16.f32 "
        "{%0,%1,%2,%3}, {%4,%5,%6,%7}, {%8,%9}, {%0,%1,%2,%3};"
        : "+f"(d[0]), "+f"(d[1]), "+f"(d[2]), "+f"(d[3])
        : "r"(a[0]), "r"(a[1]), "r"(a[2]), "r"(a[3]), "r"(b0), "r"(b1));
}
__device__ __forceinline__ void mbar_init(uint32_t addr, uint32_t count) {
    asm volatile("mbarrier.init.shared.b64 [%0], %1;" :: "r"(addr), "r"(count) : "memory");
}
__device__ __forceinline__ void mbar_expect_tx(uint32_t addr, uint32_t bytes) {
    asm volatile("mbarrier.arrive.expect_tx.shared.b64 _, [%0], %1;"
                 :: "r"(addr), "r"(bytes) : "memory");
}
__device__ __forceinline__ void mbar_arrive(uint32_t addr) {
    asm volatile("mbarrier.arrive.release.cta.shared.b64 _, [%0];" :: "r"(addr) : "memory");
}
__device__ __forceinline__ void mbar_wait(uint32_t addr, uint32_t parity) {
    asm volatile(
        "{\n\t.reg .pred P;\n\t"
        "W%=:\n\t"
        "mbarrier.try_wait.parity.acquire.cta.shared::cta.b64 P, [%0], %1, 0x989680;\n\t"
        "@!P bra W%=;\n\t"
        "}" :: "r"(addr), "r"(parity) : "memory");
}
__device__ __forceinline__ void bulk_g2s(uint32_t dst, const void* src,
                                         uint32_t bytes, uint32_t mbar) {
    asm volatile(
        "cp.async.bulk.shared::cta.global.mbarrier::complete_tx::bytes [%0], [%1], %2, [%3];"
        :: "r"(dst), "l"(src), "r"(bytes), "r"(mbar) : "memory");
}
__device__ __forceinline__ void flag_publish(int* f) {
    asm volatile("st.global.release.gpu.b32 [%0], %1;" :: "l"(f), "r"(1) : "memory");
}
__device__ __forceinline__ void flag_spin(const int* f) {
    int v;
    do {
        asm volatile("ld.global.acquire.gpu.b32 %0, [%1];" : "=r"(v) : "l"(f) : "memory");
        if (v) break;
        __nanosleep(64);
    } while (true);
}

// ---------------- W packing (+ flag reset) ----------------
__global__ void pack_w_kernel(const float* __restrict__ W) {
    int idx = blockIdx.x * blockDim.x + threadIdx.x;
    if (idx < KT2) g_flags[idx] = 0;
    if (idx >= DIN * DOUT) return;
    int k = idx / DOUT, n = idx % DOUT;
    int kt = k >> 6, kk = k & 63;
    int ch = kk >> 3, w = kk & 7;
    reinterpret_cast<__half*>(g_Wp4)[kt * 16384 + n * 64 + ((ch ^ (n & 7)) << 3) + w] =
        __float2half_rn(W[idx]);
}

// ---------------- one-kernel GCN: phase1 H = X@W+b, phase2 Out = A_hat@H ----------------
// Each CTA: phase 1 over g=0..7 (B = W tiles), publish H tiles 2b,2b+1; then
// phase 2 over g=8..263 (B = H tiles, flag-gated). One continuous mbarrier ring.
__global__ void __launch_bounds__(384, 1)
gcn_onekernel(const float* __restrict__ X,
              const float* __restrict__ Ahat,
              float* __restrict__ out,
              const float* __restrict__ bias)
{
    const int bid = blockIdx.x;
    extern __shared__ char sm[];
    const uint32_t sb = smem_u32(sm);
    const uint32_t mb = sb;
    const uint32_t tiles = sb + 1024;
    const int tid = threadIdx.x, lane = tid & 31, wid = tid >> 5;

    if (tid == 0) {
        #pragma unroll
        for (int s = 0; s < 4; s++) {
            mbar_init(mb + 8 * s, 129);      // full: 128 convert lanes + 1 tx-arrive
            mbar_init(mb + 32 + 8 * s, 8);   // empty
        }
    }
    __syncthreads();

    if (wid >= 8) {
        // ---- convert-producer warps ----
        const int w = wid - 8;
        const int lane4 = lane & 15, rh = lane >> 4;
        const int r0 = w * 32 + rh;
        const uint32_t j16 = (uint32_t)(lane4 >> 1);
        const uint32_t low8 = (uint32_t)((lane4 & 1) * 8);

        // phase 1: A = X (lda = DIN), B = W tiles
        {
            const float* src0 = X + (size_t)(bid * 128 + r0) * DIN + lane4 * 4;
            for (int g2 = 0; g2 < KT1; g2++) {
                int s = g2 & 3;
                if (g2 >= 4) mbar_wait(mb + 32 + 8 * s, ((g2 >> 2) - 1) & 1);
                uint32_t stg = tiles + s * STG2;
                if (wid == 8 && lane == 0) {
                    mbar_expect_tx(mb + 8 * s, B2SZ);
                    bulk_g2s(stg + A2SZ, g_Wp4 + (size_t)g2 * 2048, B2SZ, mb + 8 * s);
                }
                const float* srck = src0 + g2 * KC2;
                #pragma unroll
                for (int it = 0; it < 16; it++) {
                    int r = r0 + 2 * it;
                    float4 v = *reinterpret_cast<const float4*>(srck + (size_t)(2 * it) * DIN);
                    uint32_t off = (uint32_t)(r * 128) + (((j16 ^ (uint32_t)(r & 7)) << 4) + low8);
                    sts64(stg + off, pack2(v.x, v.y), pack2(v.z, v.w));
                }
                mbar_arrive(mb + 8 * s);
            }
        }
        // phase 2: A = A_hat (lda = NROWS), B = H tiles (flag-gated)
        {
            const float* src0 = Ahat + (size_t)(bid * 128 + r0) * NROWS + lane4 * 4;
            for (int g2 = KT1; g2 < KT1 + KT2; g2++) {
                int s = g2 & 3, kt = g2 - KT1;
                mbar_wait(mb + 32 + 8 * s, ((g2 >> 2) - 1) & 1);   // g2 >= 8 always
                uint32_t stg = tiles + s * STG2;
                if (wid == 8 && lane == 0) {
                    flag_spin(&g_flags[kt]);
                    asm volatile("fence.proxy.async.global;" ::: "memory");
                    mbar_expect_tx(mb + 8 * s, B2SZ);
                    bulk_g2s(stg + A2SZ, g_Hp4 + (size_t)kt * 2048, B2SZ, mb + 8 * s);
                }
                const float* srck = src0 + kt * KC2;
                #pragma unroll
                for (int it = 0; it < 16; it++) {
                    int r = r0 + 2 * it;
                    float4 v = *reinterpret_cast<const float4*>(srck + (size_t)(2 * it) * NROWS);
                    uint32_t off = (uint32_t)(r * 128) + (((j16 ^ (uint32_t)(r & 7)) << 4) + low8);
                    sts64(stg + off, pack2(v.x, v.y), pack2(v.z, v.w));
                }
                mbar_arrive(mb + 8 * s);
            }
        }
        return;
    }

    // ---- compute warps (0..7), warp tile 64x64 ----
    const int warp_m = wid & 1, warp_n = wid >> 1;
    const int g = lane >> 2, c = lane & 3;

    float acc[4][8][4];
    #pragma unroll
    for (int mt = 0; mt < 4; mt++)
        #pragma unroll
        for (int nt = 0; nt < 8; nt++)
            #pragma unroll
            for (int e = 0; e < 4; e++) acc[mt][nt][e] = 0.f;

    const int arow = lane & 15, ahi = lane >> 4, s7 = lane & 7;
    const int brow = ((lane >> 4) << 3) + (lane & 7), bhi = (lane >> 3) & 1;
    uint32_t a_row_off[4], b_row_off[4];
    #pragma unroll
    for (int mt = 0; mt < 4; mt++)
        a_row_off[mt] = (uint32_t)((warp_m * 64 + mt * 16 + arow) * 128);
    #pragma unroll
    for (int ntp = 0; ntp < 4; ntp++)
        b_row_off[ntp] = (uint32_t)(A2SZ + (warp_n * 64 + ntp * 16 + brow) * 128);

    uint32_t afr[2][4][4], bfr[2][4][4];
    auto load_frags = [&](int buf, int k16, uint32_t stg) {
        uint32_t ja = (uint32_t)(((2 * k16 + ahi) ^ s7) << 4);
        #pragma unroll
        for (int mt = 0; mt < 4; mt++)
            ldsm4(afr[buf][mt], stg + a_row_off[mt] + ja);
        uint32_t jb = (uint32_t)(((2 * k16 + bhi) ^ s7) << 4);
        #pragma unroll
        for (int ntp = 0; ntp < 4; ntp++)
            ldsm4(bfr[buf][ntp], stg + b_row_off[ntp] + jb);
    };
    auto consume_stage = [&](int g2) {
        int s = g2 & 3, ph = (g2 >> 2) & 1;
        mbar_wait(mb + 8 * s, ph);
        uint32_t stg = tiles + s * STG2;
        load_frags(0, 0, stg);
        #pragma unroll
        for (int k16 = 0; k16 < 4; k16++) {
            int cur = k16 & 1;
            if (k16 < 3) load_frags(cur ^ 1, k16 + 1, stg);
            #pragma unroll
            for (int mt = 0; mt < 4; mt++)
                #pragma unroll
                for (int nt = 0; nt < 8; nt++)
                    mma16816(acc[mt][nt], afr[cur][mt],
                             bfr[cur][nt >> 1][(nt & 1) * 2],
                             bfr[cur][nt >> 1][(nt & 1) * 2 + 1]);
        }
        if (lane == 0) mbar_arrive(mb + 32 + 8 * s);
    };

    // ---- phase 1 ----
    for (int g2 = 0; g2 < KT1; g2++) consume_stage(g2);

    // phase-1 epilogue: H = acc + bias, scattered direct to packed gmem tiles
    {
        __half* Hp = reinterpret_cast<__half*>(g_Hp4);
        int m0 = bid * 128 + warp_m * 64;
        #pragma unroll
        for (int mt = 0; mt < 4; mt++) {
            #pragma unroll
            for (int nt = 0; nt < 8; nt++) {
                int r = m0 + mt * 16 + g;            // global k index of H
                int n = warp_n * 64 + nt * 8 + c * 2;
                float bn0 = bias[n], bn1 = bias[n + 1];
                int kt = r >> 6, kk = r & 63;
                int ch = kk >> 3, w = kk & 7;
                size_t tb = (size_t)kt * 16384;
                int s0 = n & 7, s1 = (n + 1) & 7;
                Hp[tb + n * 64       + ((ch ^ s0) << 3) + w] = __float2half_rn(acc[mt][nt][0] + bn0);
                Hp[tb + (n + 1) * 64 + ((ch ^ s1) << 3) + w] = __float2half_rn(acc[mt][nt][1] + bn1);
                Hp[tb + n * 64       + (((ch + 1) ^ s0) << 3) + w] = __float2half_rn(acc[mt][nt][2] + bn0);
                Hp[tb + (n + 1) * 64 + (((ch + 1) ^ s1) << 3) + w] = __float2half_rn(acc[mt][nt][3] + bn1);
            }
        }
        asm volatile("bar.sync 1, 256;" ::: "memory");   // all compute warps' H stores done
        if (tid == 0) {
            __threadfence();
            asm volatile("fence.proxy.async.global;" ::: "memory");
            flag_publish(&g_flags[2 * bid]);
            flag_publish(&g_flags[2 * bid + 1]);
        }
        #pragma unroll
        for (int mt = 0; mt < 4; mt++)
            #pragma unroll
            for (int nt = 0; nt < 8; nt++)
                #pragma unroll
                for (int e = 0; e < 4; e++) acc[mt][nt][e] = 0.f;
    }

    // ---- phase 2 ----
    for (int g2 = KT1; g2 < KT1 + KT2; g2++) consume_stage(g2);

    // phase-2 epilogue: Out f32 row-major
    int m0 = bid * 128 + warp_m * 64;
    #pragma unroll
    for (int mt = 0; mt < 4; mt++) {
        #pragma unroll
        for (int nt = 0; nt < 8; nt++) {
            int r = m0 + mt * 16 + g;
            int n = warp_n * 64 + nt * 8 + c * 2;
            *reinterpret_cast<float2*>(out + (size_t)r * DOUT + n) =
                make_float2(acc[mt][nt][0], acc[mt][nt][1]);
            *reinterpret_cast<float2*>(out + (size_t)(r + 8) * DOUT + n) =
                make_float2(acc[mt][nt][2], acc[mt][nt][3]);
        }
    }
}

// ---------------- launch ----------------
extern "C" void kernel_launch(void* const* d_in, const int* in_sizes, int n_in,
                              void* d_out, int out_size) {
    const float* X = (const float*)d_in[0];
    const float* A = (const float*)d_in[1];
    const float* W = (const float*)d_in[2];
    const float* b = (const float*)d_in[3];
    float* out = (float*)d_out;

    cudaFuncSetAttribute(gcn_onekernel, cudaFuncAttributeMaxDynamicSharedMemorySize, SMEM2);

    pack_w_kernel<<<(DIN * DOUT + 255) / 256, 256>>>(W);
    gcn_onekernel<<<128, 384, SMEM2>>>(X, A, out, b);
}

// round 17
// speedup vs baseline: 1.2324x; 1.2324x over previous
#include <cuda_runtime.h>
#include <cuda_fp16.h>
#include <cstdint>

#define NROWS 16384
#define DIN   512
#define DOUT  256

#define KC2 64
#define KT1 (DIN / KC2)            // 8
#define KT2 (NROWS / KC2)          // 256
#define A2SZ (128 * 128)           // 16 KB  (fp16 SW128)
#define B2SZ (256 * 128)           // 32 KB
#define STG2 (A2SZ + B2SZ)         // 48 KB
#define SMEM2 (1024 + 4 * STG2)

// scratch (packed SW128 tile layout: [kt][256 n-rows x 64 halfs])
__device__ uint4 g_Wp4[DIN * DOUT / 8];    // W packed: 8 tiles
__device__ uint4 g_Hp4[NROWS * DOUT / 8];  // H packed: 256 tiles
__device__ int   g_done;                   // phase-1 completion counter

// ---------------- helpers ----------------
__device__ __forceinline__ uint32_t smem_u32(const void* p) {
    uint32_t a;
    asm("{ .reg .u64 t; cvta.to.shared.u64 t, %1; cvt.u32.u64 %0, t; }"
        : "=r"(a) : "l"(p));
    return a;
}
__device__ __forceinline__ void sts64(uint32_t a, uint32_t x, uint32_t y) {
    asm volatile("st.shared.v2.b32 [%0], {%1, %2};" :: "r"(a), "r"(x), "r"(y) : "memory");
}
__device__ __forceinline__ uint32_t pack2(float x, float y) {
    __half2 h = __floats2half2_rn(x, y);
    return *reinterpret_cast<uint32_t*>(&h);
}
__device__ __forceinline__ void ldsm4(uint32_t* r, uint32_t addr) {
    asm volatile("ldmatrix.sync.aligned.m8n8.x4.shared.b16 {%0,%1,%2,%3}, [%4];"
                 : "=r"(r[0]), "=r"(r[1]), "=r"(r[2]), "=r"(r[3]) : "r"(addr));
}
__device__ __forceinline__ void mma16816(float* d, const uint32_t* a,
                                         uint32_t b0, uint32_t b1) {
    asm volatile(
        "mma.sync.aligned.m16n8k16.row.col.f32.f16.f16.f32 "
        "{%0,%1,%2,%3}, {%4,%5,%6,%7}, {%8,%9}, {%0,%1,%2,%3};"
        : "+f"(d[0]), "+f"(d[1]), "+f"(d[2]), "+f"(d[3])
        : "r"(a[0]), "r"(a[1]), "r"(a[2]), "r"(a[3]), "r"(b0), "r"(b1));
}
__device__ __forceinline__ void mbar_init(uint32_t addr, uint32_t count) {
    asm volatile("mbarrier.init.shared.b64 [%0], %1;" :: "r"(addr), "r"(count) : "memory");
}
__device__ __forceinline__ void mbar_expect_tx(uint32_t addr, uint32_t bytes) {
    asm volatile("mbarrier.arrive.expect_tx.shared.b64 _, [%0], %1;"
                 :: "r"(addr), "r"(bytes) : "memory");
}
__device__ __forceinline__ void mbar_arrive(uint32_t addr) {
    asm volatile("mbarrier.arrive.release.cta.shared.b64 _, [%0];" :: "r"(addr) : "memory");
}
__device__ __forceinline__ void mbar_wait(uint32_t addr, uint32_t parity) {
    asm volatile(
        "{\n\t.reg .pred P;\n\t"
        "W%=:\n\t"
        "mbarrier.try_wait.parity.acquire.cta.shared::cta.b64 P, [%0], %1, 0x989680;\n\t"
        "@!P bra W%=;\n\t"
        "}" :: "r"(addr), "r"(parity) : "memory");
}
__device__ __forceinline__ void bulk_g2s(uint32_t dst, const void* src,
                                         uint32_t bytes, uint32_t mbar) {
    asm volatile(
        "cp.async.bulk.shared::cta.global.mbarrier::complete_tx::bytes [%0], [%1], %2, [%3];"
        :: "r"(dst), "l"(src), "r"(bytes), "r"(mbar) : "memory");
}

// ---------------- W packing (+ counter reset) ----------------
__global__ void pack_w_kernel(const float* __restrict__ W) {
    int idx = blockIdx.x * blockDim.x + threadIdx.x;
    if (idx == 0) g_done = 0;
    if (idx >= DIN * DOUT) return;
    int k = idx / DOUT, n = idx % DOUT;
    int kt = k >> 6, kk = k & 63;
    int ch = kk >> 3, w = kk & 7;
    reinterpret_cast<__half*>(g_Wp4)[kt * 16384 + n * 64 + ((ch ^ (n & 7)) << 3) + w] =
        __float2half_rn(W[idx]);
}

// ---------------- one-kernel GCN: phase1 H = X@W+b, phase2 Out = A_hat@H ----------------
// Single rendezvous between phases (g_done counter); phase-2 loop identical to the
// frozen gemm2 pipeline (zero per-iteration cross-CTA sync).
__global__ void __launch_bounds__(384, 1)
gcn_onekernel(const float* __restrict__ X,
              const float* __restrict__ Ahat,
              float* __restrict__ out,
              const float* __restrict__ bias)
{
    const int bid = blockIdx.x;
    extern __shared__ char sm[];
    const uint32_t sb = smem_u32(sm);
    const uint32_t mb = sb;
    const uint32_t tiles = sb + 1024;
    const int tid = threadIdx.x, lane = tid & 31, wid = tid >> 5;

    if (tid == 0) {
        #pragma unroll
        for (int s = 0; s < 4; s++) {
            mbar_init(mb + 8 * s, 129);      // full: 128 convert lanes + 1 tx-arrive
            mbar_init(mb + 32 + 8 * s, 8);   // empty
        }
    }
    __syncthreads();

    if (wid >= 8) {
        // ---- convert-producer warps ----
        const int w = wid - 8;
        const int lane4 = lane & 15, rh = lane >> 4;
        const int r0 = w * 32 + rh;
        const uint32_t j16 = (uint32_t)(lane4 >> 1);
        const uint32_t low8 = (uint32_t)((lane4 & 1) * 8);

        // phase 1: A = X (lda = DIN), B = W tiles
        {
            const float* src0 = X + (size_t)(bid * 128 + r0) * DIN + lane4 * 4;
            for (int g2 = 0; g2 < KT1; g2++) {
                int s = g2 & 3;
                if (g2 >= 4) mbar_wait(mb + 32 + 8 * s, ((g2 >> 2) - 1) & 1);
                uint32_t stg = tiles + s * STG2;
                if (wid == 8 && lane == 0) {
                    mbar_expect_tx(mb + 8 * s, B2SZ);
                    bulk_g2s(stg + A2SZ, g_Wp4 + (size_t)g2 * 2048, B2SZ, mb + 8 * s);
                }
                const float* srck = src0 + g2 * KC2;
                #pragma unroll
                for (int it = 0; it < 16; it++) {
                    int r = r0 + 2 * it;
                    float4 v = *reinterpret_cast<const float4*>(srck + (size_t)(2 * it) * DIN);
                    uint32_t off = (uint32_t)(r * 128) + (((j16 ^ (uint32_t)(r & 7)) << 4) + low8);
                    sts64(stg + off, pack2(v.x, v.y), pack2(v.z, v.w));
                }
                mbar_arrive(mb + 8 * s);
            }
        }
        // rendezvous: wait for ALL CTAs' phase-1 H stores, once
        if (wid == 8 && lane == 0) {
            int v;
            do {
                asm volatile("ld.global.acquire.gpu.b32 %0, [%1];"
                             : "=r"(v) : "l"(&g_done) : "memory");
                if (v >= 128) break;
                __nanosleep(128);
            } while (true);
            asm volatile("fence.proxy.async.global;" ::: "memory");
        }
        // phase 2: A = A_hat (lda = NROWS), B = H tiles (no per-tile sync)
        {
            const float* src0 = Ahat + (size_t)(bid * 128 + r0) * NROWS + lane4 * 4;
            for (int g2 = KT1; g2 < KT1 + KT2; g2++) {
                int s = g2 & 3, kt = g2 - KT1;
                mbar_wait(mb + 32 + 8 * s, ((g2 >> 2) - 1) & 1);   // g2 >= 8 always
                uint32_t stg = tiles + s * STG2;
                if (wid == 8 && lane == 0) {
                    mbar_expect_tx(mb + 8 * s, B2SZ);
                    bulk_g2s(stg + A2SZ, g_Hp4 + (size_t)kt * 2048, B2SZ, mb + 8 * s);
                }
                const float* srck = src0 + kt * KC2;
                #pragma unroll
                for (int it = 0; it < 16; it++) {
                    int r = r0 + 2 * it;
                    float4 v = *reinterpret_cast<const float4*>(srck + (size_t)(2 * it) * NROWS);
                    uint32_t off = (uint32_t)(r * 128) + (((j16 ^ (uint32_t)(r & 7)) << 4) + low8);
                    sts64(stg + off, pack2(v.x, v.y), pack2(v.z, v.w));
                }
                mbar_arrive(mb + 8 * s);
            }
        }
        return;
    }

    // ---- compute warps (0..7), warp tile 64x64 ----
    const int warp_m = wid & 1, warp_n = wid >> 1;
    const int g = lane >> 2, c = lane & 3;

    float acc[4][8][4];
    #pragma unroll
    for (int mt = 0; mt < 4; mt++)
        #pragma unroll
        for (int nt = 0; nt < 8; nt++)
            #pragma unroll
            for (int e = 0; e < 4; e++) acc[mt][nt][e] = 0.f;

    const int arow = lane & 15, ahi = lane >> 4, s7 = lane & 7;
    const int brow = ((lane >> 4) << 3) + (lane & 7), bhi = (lane >> 3) & 1;
    uint32_t a_row_off[4], b_row_off[4];
    #pragma unroll
    for (int mt = 0; mt < 4; mt++)
        a_row_off[mt] = (uint32_t)((warp_m * 64 + mt * 16 + arow) * 128);
    #pragma unroll
    for (int ntp = 0; ntp < 4; ntp++)
        b_row_off[ntp] = (uint32_t)(A2SZ + (warp_n * 64 + ntp * 16 + brow) * 128);

    uint32_t afr[2][4][4], bfr[2][4][4];
    auto load_frags = [&](int buf, int k16, uint32_t stg) {
        uint32_t ja = (uint32_t)(((2 * k16 + ahi) ^ s7) << 4);
        #pragma unroll
        for (int mt = 0; mt < 4; mt++)
            ldsm4(afr[buf][mt], stg + a_row_off[mt] + ja);
        uint32_t jb = (uint32_t)(((2 * k16 + bhi) ^ s7) << 4);
        #pragma unroll
        for (int ntp = 0; ntp < 4; ntp++)
            ldsm4(bfr[buf][ntp], stg + b_row_off[ntp] + jb);
    };
    auto consume_stage = [&](int g2) {
        int s = g2 & 3, ph = (g2 >> 2) & 1;
        mbar_wait(mb + 8 * s, ph);
        uint32_t stg = tiles + s * STG2;
        load_frags(0, 0, stg);
        #pragma unroll
        for (int k16 = 0; k16 < 4; k16++) {
            int cur = k16 & 1;
            if (k16 < 3) load_frags(cur ^ 1, k16 + 1, stg);
            #pragma unroll
            for (int mt = 0; mt < 4; mt++)
                #pragma unroll
                for (int nt = 0; nt < 8; nt++)
                    mma16816(acc[mt][nt], afr[cur][mt],
                             bfr[cur][nt >> 1][(nt & 1) * 2],
                             bfr[cur][nt >> 1][(nt & 1) * 2 + 1]);
        }
        if (lane == 0) mbar_arrive(mb + 32 + 8 * s);
    };

    // ---- phase 1 ----
    for (int g2 = 0; g2 < KT1; g2++) consume_stage(g2);

    // phase-1 epilogue: H = acc + bias, scattered direct to packed gmem tiles
    {
        __half* Hp = reinterpret_cast<__half*>(g_Hp4);
        int m0 = bid * 128 + warp_m * 64;
        #pragma unroll
        for (int mt = 0; mt < 4; mt++) {
            #pragma unroll
            for (int nt = 0; nt < 8; nt++) {
                int r = m0 + mt * 16 + g;            // global k index of H
                int n = warp_n * 64 + nt * 8 + c * 2;
                float bn0 = bias[n], bn1 = bias[n + 1];
                int kt = r >> 6, kk = r & 63;
                int ch = kk >> 3, w = kk & 7;
                size_t tb = (size_t)kt * 16384;
                int s0 = n & 7, s1 = (n + 1) & 7;
                Hp[tb + n * 64       + ((ch ^ s0) << 3) + w] = __float2half_rn(acc[mt][nt][0] + bn0);
                Hp[tb + (n + 1) * 64 + ((ch ^ s1) << 3) + w] = __float2half_rn(acc[mt][nt][1] + bn1);
                Hp[tb + n * 64       + (((ch + 1) ^ s0) << 3) + w] = __float2half_rn(acc[mt][nt][2] + bn0);
                Hp[tb + (n + 1) * 64 + (((ch + 1) ^ s1) << 3) + w] = __float2half_rn(acc[mt][nt][3] + bn1);
            }
        }
        asm volatile("bar.sync 1, 256;" ::: "memory");   // all compute warps' H stores done
        if (tid == 0) {
            __threadfence();
            atomicAdd(&g_done, 1);   // release via preceding threadfence; counter chain
        }
        #pragma unroll
        for (int mt = 0; mt < 4; mt++)
            #pragma unroll
            for (int nt = 0; nt < 8; nt++)
                #pragma unroll
                for (int e = 0; e < 4; e++) acc[mt][nt][e] = 0.f;
    }

    // ---- phase 2 ----
    for (int g2 = KT1; g2 < KT1 + KT2; g2++) consume_stage(g2);

    // phase-2 epilogue: Out f32 row-major
    int m0 = bid * 128 + warp_m * 64;
    #pragma unroll
    for (int mt = 0; mt < 4; mt++) {
        #pragma unroll
        for (int nt = 0; nt < 8; nt++) {
            int r = m0 + mt * 16 + g;
            int n = warp_n * 64 + nt * 8 + c * 2;
            *reinterpret_cast<float2*>(out + (size_t)r * DOUT + n) =
                make_float2(acc[mt][nt][0], acc[mt][nt][1]);
            *reinterpret_cast<float2*>(out + (size_t)(r + 8) * DOUT + n) =
                make_float2(acc[mt][nt][2], acc[mt][nt][3]);
        }
    }
}

// ---------------- launch ----------------
extern "C" void kernel_launch(void* const* d_in, const int* in_sizes, int n_in,
                              void* d_out, int out_size) {
    const float* X = (const float*)d_in[0];
    const float* A = (const float*)d_in[1];
    const float* W = (const float*)d_in[2];
    const float* b = (const float*)d_in[3];
    float* out = (float*)d_out;

    cudaFuncSetAttribute(gcn_onekernel, cudaFuncAttributeMaxDynamicSharedMemorySize, SMEM2);

    pack_w_kernel<<<(DIN * DOUT + 255) / 256, 256>>>(W);
    gcn_onekernel<<<128, 384, SMEM2>>>(X, A, out, b);
}